// round 9
// baseline (speedup 1.0000x reference)
#include <cuda_runtime.h>
#include <cuda_bf16.h>
#include <math.h>
#include <stdint.h>

#define N_NODES 50000
#define N_EDGES 800000

// ---------------- scratch (static device globals; no runtime alloc) --------
__device__ int   g_counts[N_NODES];
__device__ int   g_offsets[N_NODES + 1];
__device__ int   g_cursor[N_NODES];
__device__ int   g_csr[N_EDGES];
__device__ float g_h64[(size_t)N_NODES * 64];
__device__ __nv_bfloat16 g_xf[(size_t)N_NODES * 256];   // bf16 feature matrix (gathered per edge)
__device__ float g_hA [(size_t)N_NODES * 256];
__device__ float g_hB [(size_t)N_NODES * 256];
__device__ float g_esrc[N_NODES * 4];
__device__ float g_edst[N_NODES * 4];
__device__ float g_pool[64];

// ---------------- CSR build ------------------------------------------------
__global__ void zero_kernel() {
    int i = blockIdx.x * blockDim.x + threadIdx.x;
    if (i < N_NODES) g_counts[i] = 0;
    if (i < 64) g_pool[i] = 0.f;
}

__global__ void hist_kernel(const int* __restrict__ dst) {
    int i = blockIdx.x * blockDim.x + threadIdx.x;
    if (i < N_EDGES) atomicAdd(&g_counts[dst[i]], 1);
}

__global__ void scan_kernel() {
    __shared__ int ssum[1024];
    int t = threadIdx.x;
    const int CH = (N_NODES + 1023) / 1024;
    int base = t * CH;
    int s = 0;
    for (int c = 0; c < CH; c++) {
        int idx = base + c;
        if (idx < N_NODES) s += g_counts[idx];
    }
    ssum[t] = s;
    __syncthreads();
    for (int off = 1; off < 1024; off <<= 1) {
        int v = (t >= off) ? ssum[t - off] : 0;
        __syncthreads();
        ssum[t] += v;
        __syncthreads();
    }
    int run = (t == 0) ? 0 : ssum[t - 1];
    for (int c = 0; c < CH; c++) {
        int idx = base + c;
        if (idx < N_NODES) {
            g_offsets[idx] = run;
            g_cursor[idx]  = run;
            run += g_counts[idx];
        }
    }
    if (t == 1023) g_offsets[N_NODES] = ssum[1023];
}

__global__ void scatter_kernel(const int* __restrict__ src, const int* __restrict__ dst) {
    int i = blockIdx.x * blockDim.x + threadIdx.x;
    if (i < N_EDGES) {
        int p = atomicAdd(&g_cursor[dst[i]], 1);
        g_csr[p] = src[i];
    }
}

// ---------------- TF32 tensor-core GEMM (R2 layout) -------------------------
// C[MxN] = A[MxK] * B[KxN], row-major.
// mode 1: fp32 store +bias+elu (input MLP)
// mode 2: bf16 store to Cb + fused e-logits for head = blockIdx.x (BN==64==D)
__device__ __forceinline__ float tf32r(float x) {
    float y;
    asm("cvt.rna.tf32.f32 %0, %1;" : "=f"(y) : "f"(x));
    return y;
}

__device__ __forceinline__ void mma_tf32(float* c, const uint32_t* a, uint32_t b0, uint32_t b1) {
    asm volatile(
        "mma.sync.aligned.m16n8k8.row.col.f32.tf32.tf32.f32 "
        "{%0,%1,%2,%3},{%4,%5,%6,%7},{%8,%9},{%0,%1,%2,%3};"
        : "+f"(c[0]), "+f"(c[1]), "+f"(c[2]), "+f"(c[3])
        : "r"(a[0]), "r"(a[1]), "r"(a[2]), "r"(a[3]), "r"(b0), "r"(b1));
}

__global__ __launch_bounds__(256) void tf32gemm_kernel(
        const float* __restrict__ A, const float* __restrict__ B,
        const float* __restrict__ bias, float* __restrict__ C,
        __nv_bfloat16* __restrict__ Cb,
        int M, int N, int K, int mode,
        const float* __restrict__ a_s, const float* __restrict__ a_d, int eH) {
    const int BM = 128, BN = 64, BK = 32;
    __shared__ float As[BK][BM + 4];   // [k][m]
    __shared__ float Bs[BK][BN + 4];   // [k][n]
    __shared__ float eredS[128], eredD[128];

    int tx = threadIdx.x;
    int bm = blockIdx.y * BM;
    int bn = blockIdx.x * BN;
    int wid = tx >> 5, lane = tx & 31;
    int wm = (wid >> 1) * 32;          // warp m offset within block
    int wn = (wid & 1) * 32;           // warp n offset within block
    const int gid = lane >> 2;         // 0..7
    const int tig = lane & 3;          // 0..3

    if (mode == 2 && tx < 128) { eredS[tx] = 0.f; eredD[tx] = 0.f; }

    float acc[2][4][4];
#pragma unroll
    for (int mt = 0; mt < 2; mt++)
#pragma unroll
        for (int nt = 0; nt < 4; nt++)
#pragma unroll
            for (int q = 0; q < 4; q++) acc[mt][nt][q] = 0.f;

    const float4 z4 = make_float4(0.f, 0.f, 0.f, 0.f);
    float4 pa[4], pb[2];

    // prefetch tile 0
#pragma unroll
    for (int q = 0; q < 4; q++) {
        int idx = tx + q * 256;
        int row = idx >> 3;
        int kq  = (idx & 7) * 4;
        int gm  = bm + row;
        pa[q] = (gm < M) ? *(const float4*)&A[(size_t)gm * K + kq] : z4;
    }
#pragma unroll
    for (int q = 0; q < 2; q++) {
        int idx = tx + q * 256;
        int row = idx >> 4;
        int col = (idx & 15) * 4;
        pb[q] = *(const float4*)&B[(size_t)row * N + bn + col];
    }

    for (int k0 = 0; k0 < K; k0 += BK) {
        // commit prefetched tile (tf32-rounded) into smem
#pragma unroll
        for (int q = 0; q < 4; q++) {
            int idx = tx + q * 256;
            int row = idx >> 3;
            int kq  = (idx & 7) * 4;
            As[kq + 0][row] = tf32r(pa[q].x);
            As[kq + 1][row] = tf32r(pa[q].y);
            As[kq + 2][row] = tf32r(pa[q].z);
            As[kq + 3][row] = tf32r(pa[q].w);
        }
#pragma unroll
        for (int q = 0; q < 2; q++) {
            int idx = tx + q * 256;
            int row = idx >> 4;
            int col = (idx & 15) * 4;
            Bs[row][col + 0] = tf32r(pb[q].x);
            Bs[row][col + 1] = tf32r(pb[q].y);
            Bs[row][col + 2] = tf32r(pb[q].z);
            Bs[row][col + 3] = tf32r(pb[q].w);
        }
        __syncthreads();

        // prefetch next tile
        if (k0 + BK < K) {
            int kk = k0 + BK;
#pragma unroll
            for (int q = 0; q < 4; q++) {
                int idx = tx + q * 256;
                int row = idx >> 3;
                int kq  = (idx & 7) * 4;
                int gm  = bm + row;
                pa[q] = (gm < M) ? *(const float4*)&A[(size_t)gm * K + kk + kq] : z4;
            }
#pragma unroll
            for (int q = 0; q < 2; q++) {
                int idx = tx + q * 256;
                int row = idx >> 4;
                int col = (idx & 15) * 4;
                pb[q] = *(const float4*)&B[(size_t)(kk + row) * N + bn + col];
            }
        }

        // 4 k-steps of 8
#pragma unroll
        for (int ks = 0; ks < 4; ks++) {
            int kb = ks * 8;
            uint32_t af[2][4];
#pragma unroll
            for (int mt = 0; mt < 2; mt++) {
                int r = wm + mt * 16 + gid;
                af[mt][0] = __float_as_uint(As[kb + tig][r]);
                af[mt][1] = __float_as_uint(As[kb + tig][r + 8]);
                af[mt][2] = __float_as_uint(As[kb + tig + 4][r]);
                af[mt][3] = __float_as_uint(As[kb + tig + 4][r + 8]);
            }
#pragma unroll
            for (int nt = 0; nt < 4; nt++) {
                int c = wn + nt * 8 + gid;
                uint32_t b0 = __float_as_uint(Bs[kb + tig][c]);
                uint32_t b1 = __float_as_uint(Bs[kb + tig + 4][c]);
                mma_tf32(acc[0][nt], af[0], b0, b1);
                mma_tf32(acc[1][nt], af[1], b0, b1);
            }
        }
        __syncthreads();
    }

    // epilogue
#pragma unroll
    for (int mt = 0; mt < 2; mt++) {
#pragma unroll
        for (int half = 0; half < 2; half++) {
            int m = bm + wm + mt * 16 + gid + half * 8;
            if (m >= M) continue;
#pragma unroll
            for (int nt = 0; nt < 4; nt++) {
                int n = bn + wn + nt * 8 + 2 * tig;
                float v0 = acc[mt][nt][half * 2 + 0];
                float v1 = acc[mt][nt][half * 2 + 1];
                if (mode == 1) {
                    v0 += bias[n];
                    v1 += bias[n + 1];
                    v0 = v0 > 0.f ? v0 : expm1f(v0);
                    v1 = v1 > 0.f ? v1 : expm1f(v1);
                    *(float2*)&C[(size_t)m * N + n] = make_float2(v0, v1);
                } else {
                    *(__nv_bfloat162*)&Cb[(size_t)m * N + n] = __floats2bfloat162_rn(v0, v1);
                }
            }
        }
    }

    if (mode == 2) {
        int head = blockIdx.x;
        const float* asv = a_s + head * 64;
        const float* adv = a_d + head * 64;
#pragma unroll
        for (int mt = 0; mt < 2; mt++) {
#pragma unroll
            for (int half = 0; half < 2; half++) {
                float ps = 0.f, pd = 0.f;
#pragma unroll
                for (int nt = 0; nt < 4; nt++) {
                    int ln = wn + nt * 8 + 2 * tig;
                    float v0 = acc[mt][nt][half * 2 + 0];
                    float v1 = acc[mt][nt][half * 2 + 1];
                    ps += v0 * asv[ln] + v1 * asv[ln + 1];
                    pd += v0 * adv[ln] + v1 * adv[ln + 1];
                }
                ps += __shfl_xor_sync(0xffffffffu, ps, 1);
                ps += __shfl_xor_sync(0xffffffffu, ps, 2);
                pd += __shfl_xor_sync(0xffffffffu, pd, 1);
                pd += __shfl_xor_sync(0xffffffffu, pd, 2);
                if (tig == 0) {
                    int rl = wm + mt * 16 + half * 8 + gid;  // 0..127
                    atomicAdd(&eredS[rl], ps);
                    atomicAdd(&eredD[rl], pd);
                }
            }
        }
        __syncthreads();
        if (tx < 128) {
            int m = bm + tx;
            if (m < M) {
                g_esrc[m * eH + head] = eredS[tx];
                g_edst[m * eH + head] = eredD[tx];
            }
        }
    }
}

// ---------------- GAT aggregation: warp per destination node ---------------
// xf is bf16; accumulation in fp32.
__device__ __forceinline__ float2 b2f(uint32_t u) {
    __nv_bfloat162 h;
    *reinterpret_cast<uint32_t*>(&h) = u;
    return __bfloat1622float2(h);
}

template <int H, int D>
__global__ void gat_agg_kernel(const __nv_bfloat16* __restrict__ xf,
                               const float* __restrict__ bias,
                               float* __restrict__ out) {
    constexpr int F = H * D;
    constexpr int FP = F / 32;       // features per lane (8 or 2)
    int gw = (blockIdx.x * blockDim.x + threadIdx.x) >> 5;
    int lane = threadIdx.x & 31;
    if (gw >= N_NODES) return;
    const int i = gw;
    const int beg = g_offsets[i], end = g_offsets[i + 1];

    float edst_i[H], eself[H], m[H];
#pragma unroll
    for (int h = 0; h < H; h++) {
        edst_i[h] = g_edst[i * H + h];
        float v = g_esrc[i * H + h] + edst_i[h];
        v = v > 0.f ? v : 0.2f * v;
        eself[h] = v;
        m[h] = v;  // self-loop participates in max
    }
    // pass 1: segment max over incoming edges (scalar logits only)
    for (int k = beg + lane; k < end; k += 32) {
        int s = g_csr[k];
#pragma unroll
        for (int h = 0; h < H; h++) {
            float v = g_esrc[s * H + h] + edst_i[h];
            v = v > 0.f ? v : 0.2f * v;
            m[h] = fmaxf(m[h], v);
        }
    }
#pragma unroll
    for (int h = 0; h < H; h++)
#pragma unroll
        for (int off = 16; off; off >>= 1)
            m[h] = fmaxf(m[h], __shfl_xor_sync(0xffffffffu, m[h], off));

    // pass 2: exp-weights, running sum, warp-cooperative bf16 feature gather
    float acc[FP];
#pragma unroll
    for (int q = 0; q < FP; q++) acc[q] = 0.f;
    float ssum[H];
#pragma unroll
    for (int h = 0; h < H; h++) ssum[h] = 0.f;
    const int myh = (lane * FP) / D;

    for (int base = beg; base < end; base += 32) {
        int k = base + lane;
        int cnt = min(32, end - base);
        int s = 0;
        float w[H];
#pragma unroll
        for (int h = 0; h < H; h++) w[h] = 0.f;
        if (k < end) {
            s = g_csr[k];
#pragma unroll
            for (int h = 0; h < H; h++) {
                float v = g_esrc[s * H + h] + edst_i[h];
                v = v > 0.f ? v : 0.2f * v;
                float ww = __expf(v - m[h]);
                w[h] = ww;
                ssum[h] += ww;
            }
        }
        for (int j = 0; j < cnt; j++) {
            int sj = __shfl_sync(0xffffffffu, s, j);
            float wh;
            if constexpr (H == 4) {
                float w0 = __shfl_sync(0xffffffffu, w[0], j);
                float w1 = __shfl_sync(0xffffffffu, w[1], j);
                float w2 = __shfl_sync(0xffffffffu, w[2], j);
                float w3 = __shfl_sync(0xffffffffu, w[3], j);
                wh = (myh == 0) ? w0 : (myh == 1) ? w1 : (myh == 2) ? w2 : w3;
            } else {
                wh = __shfl_sync(0xffffffffu, w[0], j);
            }
            const __nv_bfloat16* xr = xf + (size_t)sj * F;
            if constexpr (FP == 8) {
                uint4 r = ((const uint4*)xr)[lane];
                float2 f0 = b2f(r.x), f1 = b2f(r.y), f2 = b2f(r.z), f3 = b2f(r.w);
                acc[0] += wh * f0.x; acc[1] += wh * f0.y;
                acc[2] += wh * f1.x; acc[3] += wh * f1.y;
                acc[4] += wh * f2.x; acc[5] += wh * f2.y;
                acc[6] += wh * f3.x; acc[7] += wh * f3.y;
            } else {
                uint32_t r = ((const uint32_t*)xr)[lane];
                float2 f = b2f(r);
                acc[0] += wh * f.x; acc[1] += wh * f.y;
            }
        }
    }
    // total exp-sum across the warp, then fold in self-loop
#pragma unroll
    for (int h = 0; h < H; h++)
#pragma unroll
        for (int off = 16; off; off >>= 1)
            ssum[h] += __shfl_xor_sync(0xffffffffu, ssum[h], off);
    float wself[H];
#pragma unroll
    for (int h = 0; h < H; h++) {
        wself[h] = __expf(eself[h] - m[h]);
        ssum[h] += wself[h];
    }
    {
        float wh;
        if constexpr (H == 4)
            wh = (myh == 0) ? wself[0] : (myh == 1) ? wself[1] : (myh == 2) ? wself[2] : wself[3];
        else
            wh = wself[0];
        const __nv_bfloat16* xr = xf + (size_t)i * F;
        if constexpr (FP == 8) {
            uint4 r = ((const uint4*)xr)[lane];
            float2 f0 = b2f(r.x), f1 = b2f(r.y), f2 = b2f(r.z), f3 = b2f(r.w);
            acc[0] += wh * f0.x; acc[1] += wh * f0.y;
            acc[2] += wh * f1.x; acc[3] += wh * f1.y;
            acc[4] += wh * f2.x; acc[5] += wh * f2.y;
            acc[6] += wh * f3.x; acc[7] += wh * f3.y;
        } else {
            uint32_t r = ((const uint32_t*)xr)[lane];
            float2 f = b2f(r);
            acc[0] += wh * f.x; acc[1] += wh * f.y;
        }
    }
    float denom;
    if constexpr (H == 4)
        denom = (myh == 0) ? ssum[0] : (myh == 1) ? ssum[1] : (myh == 2) ? ssum[2] : ssum[3];
    else
        denom = ssum[0];
    float inv = 1.f / denom;
#pragma unroll
    for (int q = 0; q < FP; q++) {
        int f = lane * FP + q;
        float v = acc[q] * inv + bias[f];
        v = v > 0.f ? v : expm1f(v);   // elu applied after every GAT layer
        out[(size_t)i * F + f] = v;
    }
}

// ---------------- global mean pool + output projection ---------------------
__global__ void pool_kernel(const float* __restrict__ h) {
    __shared__ float sacc[64];
    int t = threadIdx.x;
    if (t < 64) sacc[t] = 0.f;
    __syncthreads();
    int col = t & 63;
    int rpb = blockDim.x >> 6;  // rows per block pass
    float a = 0.f;
    for (int r = blockIdx.x * rpb + (t >> 6); r < N_NODES; r += gridDim.x * rpb)
        a += h[(size_t)r * 64 + col];
    atomicAdd(&sacc[col], a);
    __syncthreads();
    if (t < 64) atomicAdd(&g_pool[t], sacc[t]);
}

__global__ void final_kernel(const float* __restrict__ w_out,
                             const float* __restrict__ b_out,
                             float* __restrict__ out) {
    int j = threadIdx.x;  // 0..127
    float s = b_out[j];
    const float invn = 1.f / (float)N_NODES;
    for (int k = 0; k < 64; k++)
        s += g_pool[k] * invn * w_out[k * 128 + j];
    out[j] = s;
}

// ---------------- launcher -------------------------------------------------
extern "C" void kernel_launch(void* const* d_in, const int* in_sizes, int n_in,
                              void* d_out, int out_size) {
    const float* x     = (const float*)d_in[0];
    const int*   ei    = (const int*)d_in[1];
    const int*   src   = ei;
    const int*   dst   = ei + N_EDGES;
    const float* w_in  = (const float*)d_in[2];
    const float* b_in  = (const float*)d_in[3];
    const float* W0    = (const float*)d_in[4];
    const float* as0   = (const float*)d_in[5];
    const float* ad0   = (const float*)d_in[6];
    const float* bb0   = (const float*)d_in[7];
    const float* W1    = (const float*)d_in[8];
    const float* as1   = (const float*)d_in[9];
    const float* ad1   = (const float*)d_in[10];
    const float* bb1   = (const float*)d_in[11];
    const float* W2    = (const float*)d_in[12];
    const float* as2   = (const float*)d_in[13];
    const float* ad2   = (const float*)d_in[14];
    const float* bb2   = (const float*)d_in[15];
    const float* w_out = (const float*)d_in[16];
    const float* b_out = (const float*)d_in[17];
    float* out = (float*)d_out;

    void *p_h64, *p_xf, *p_hA, *p_hB;
    cudaGetSymbolAddress(&p_h64, g_h64);
    cudaGetSymbolAddress(&p_xf,  g_xf);
    cudaGetSymbolAddress(&p_hA,  g_hA);
    cudaGetSymbolAddress(&p_hB,  g_hB);
    float* h64 = (float*)p_h64;
    __nv_bfloat16* xf = (__nv_bfloat16*)p_xf;
    float* hA  = (float*)p_hA;
    float* hB  = (float*)p_hB;

    const int EB = (N_EDGES + 255) / 256;
    const int NB = (N_NODES + 255) / 256;
    const int MY = (N_NODES + 127) / 128;   // 391 row-blocks of 128
    const int WARPB = N_NODES / 8;          // 6250 blocks of 8 warps

    // CSR build (per-launch; deterministic workload)
    zero_kernel<<<NB, 256>>>();
    hist_kernel<<<EB, 256>>>(dst);
    scan_kernel<<<1, 1024>>>();
    scatter_kernel<<<EB, 256>>>(src, dst);

    // input MLP: h64 = elu(x @ w_in + b_in)   (fp32 out)
    tf32gemm_kernel<<<dim3(1, MY), 256>>>(x, w_in, b_in, h64, nullptr,
                                          N_NODES, 64, 256, 1, nullptr, nullptr, 0);

    // GAT layer 0 (H=4, D=64): GEMM -> bf16 xf + fused e-logits
    tf32gemm_kernel<<<dim3(4, MY), 256>>>(h64, W0, nullptr, nullptr, xf,
                                          N_NODES, 256, 64, 2, as0, ad0, 4);
    gat_agg_kernel<4, 64><<<WARPB, 256>>>(xf, bb0, hA);

    // GAT layer 1 (H=4, D=64)
    tf32gemm_kernel<<<dim3(4, MY), 256>>>(hA, W1, nullptr, nullptr, xf,
                                          N_NODES, 256, 256, 2, as1, ad1, 4);
    gat_agg_kernel<4, 64><<<WARPB, 256>>>(xf, bb1, hB);

    // GAT layer 2 (H=1, D=64)
    tf32gemm_kernel<<<dim3(1, MY), 256>>>(hB, W2, nullptr, nullptr, xf,
                                          N_NODES, 64, 256, 2, as2, ad2, 1);
    gat_agg_kernel<1, 64><<<WARPB, 256>>>(xf, bb2, h64);

    // global mean pool + out projection
    pool_kernel<<<256, 256>>>(h64);
    final_kernel<<<1, 128>>>(w_out, b_out, out);
}

// round 10
// speedup vs baseline: 1.4208x; 1.4208x over previous
#include <cuda_runtime.h>
#include <cuda_bf16.h>
#include <math.h>
#include <stdint.h>

#define N_NODES 50000
#define N_EDGES 800000

// ---------------- scratch (static device globals; no runtime alloc) --------
__device__ int   g_counts[N_NODES];
__device__ int   g_offsets[N_NODES + 1];
__device__ int   g_cursor[N_NODES];
__device__ int   g_csr[N_EDGES];
__device__ float g_h64[(size_t)N_NODES * 64];
__device__ __nv_bfloat16 g_xf[(size_t)N_NODES * 256];   // bf16 features (edge-gathered)
__device__ float g_hA [(size_t)N_NODES * 256];
__device__ float g_hB [(size_t)N_NODES * 256];
__device__ float g_esrc[N_NODES * 4];
__device__ float g_edst[N_NODES * 4];
__device__ float g_pool[64];

// ---------------- CSR build ------------------------------------------------
__global__ void zero_kernel() {
    int i = blockIdx.x * blockDim.x + threadIdx.x;
    if (i < N_NODES) g_counts[i] = 0;
    if (i < 64) g_pool[i] = 0.f;
}

__global__ void hist_kernel(const int* __restrict__ dst) {
    int i = blockIdx.x * blockDim.x + threadIdx.x;
    if (i < N_EDGES) atomicAdd(&g_counts[dst[i]], 1);
}

__global__ void scan_kernel() {
    __shared__ int ssum[1024];
    int t = threadIdx.x;
    const int CH = (N_NODES + 1023) / 1024;
    int base = t * CH;
    int s = 0;
    for (int c = 0; c < CH; c++) {
        int idx = base + c;
        if (idx < N_NODES) s += g_counts[idx];
    }
    ssum[t] = s;
    __syncthreads();
    for (int off = 1; off < 1024; off <<= 1) {
        int v = (t >= off) ? ssum[t - off] : 0;
        __syncthreads();
        ssum[t] += v;
        __syncthreads();
    }
    int run = (t == 0) ? 0 : ssum[t - 1];
    for (int c = 0; c < CH; c++) {
        int idx = base + c;
        if (idx < N_NODES) {
            g_offsets[idx] = run;
            g_cursor[idx]  = run;
            run += g_counts[idx];
        }
    }
    if (t == 1023) g_offsets[N_NODES] = ssum[1023];
}

__global__ void scatter_kernel(const int* __restrict__ src, const int* __restrict__ dst) {
    int i = blockIdx.x * blockDim.x + threadIdx.x;
    if (i < N_EDGES) {
        int p = atomicAdd(&g_cursor[dst[i]], 1);
        g_csr[p] = src[i];
    }
}

// ---------------- TF32 tensor-core GEMM (exact R2 structure) ----------------
// C[MxN] = A[MxK] * B[KxN], row-major.
// mode 0: plain bf16 store to Cb; mode 1: fp32 store +bias+elu.
__device__ __forceinline__ float tf32r(float x) {
    float y;
    asm("cvt.rna.tf32.f32 %0, %1;" : "=f"(y) : "f"(x));
    return y;
}

__device__ __forceinline__ void mma_tf32(float* c, const uint32_t* a, uint32_t b0, uint32_t b1) {
    asm volatile(
        "mma.sync.aligned.m16n8k8.row.col.f32.tf32.tf32.f32 "
        "{%0,%1,%2,%3},{%4,%5,%6,%7},{%8,%9},{%0,%1,%2,%3};"
        : "+f"(c[0]), "+f"(c[1]), "+f"(c[2]), "+f"(c[3])
        : "r"(a[0]), "r"(a[1]), "r"(a[2]), "r"(a[3]), "r"(b0), "r"(b1));
}

__global__ __launch_bounds__(256) void tf32gemm_kernel(
        const float* __restrict__ A, const float* __restrict__ B,
        const float* __restrict__ bias, float* __restrict__ C,
        __nv_bfloat16* __restrict__ Cb,
        int M, int N, int K, int mode) {
    const int BM = 128, BN = 64, BK = 32;
    __shared__ float As[BK][BM + 4];   // [k][m]
    __shared__ float Bs[BK][BN + 4];   // [k][n]
    int tx = threadIdx.x;
    int bm = blockIdx.y * BM;
    int bn = blockIdx.x * BN;
    int wid = tx >> 5, lane = tx & 31;
    int wm = (wid >> 1) * 32;          // warp m offset within block
    int wn = (wid & 1) * 32;           // warp n offset within block
    const int gid = lane >> 2;         // 0..7
    const int tig = lane & 3;          // 0..3

    float acc[2][4][4];
#pragma unroll
    for (int mt = 0; mt < 2; mt++)
#pragma unroll
        for (int nt = 0; nt < 4; nt++)
#pragma unroll
            for (int q = 0; q < 4; q++) acc[mt][nt][q] = 0.f;

    const float4 z4 = make_float4(0.f, 0.f, 0.f, 0.f);
    float4 pa[4], pb[2];

    // prefetch tile 0
#pragma unroll
    for (int q = 0; q < 4; q++) {
        int idx = tx + q * 256;
        int row = idx >> 3;
        int kq  = (idx & 7) * 4;
        int gm  = bm + row;
        pa[q] = (gm < M) ? *(const float4*)&A[(size_t)gm * K + kq] : z4;
    }
#pragma unroll
    for (int q = 0; q < 2; q++) {
        int idx = tx + q * 256;
        int row = idx >> 4;
        int col = (idx & 15) * 4;
        pb[q] = *(const float4*)&B[(size_t)row * N + bn + col];
    }

    for (int k0 = 0; k0 < K; k0 += BK) {
        // commit prefetched tile (tf32-rounded) into smem
#pragma unroll
        for (int q = 0; q < 4; q++) {
            int idx = tx + q * 256;
            int row = idx >> 3;
            int kq  = (idx & 7) * 4;
            As[kq + 0][row] = tf32r(pa[q].x);
            As[kq + 1][row] = tf32r(pa[q].y);
            As[kq + 2][row] = tf32r(pa[q].z);
            As[kq + 3][row] = tf32r(pa[q].w);
        }
#pragma unroll
        for (int q = 0; q < 2; q++) {
            int idx = tx + q * 256;
            int row = idx >> 4;
            int col = (idx & 15) * 4;
            Bs[row][col + 0] = tf32r(pb[q].x);
            Bs[row][col + 1] = tf32r(pb[q].y);
            Bs[row][col + 2] = tf32r(pb[q].z);
            Bs[row][col + 3] = tf32r(pb[q].w);
        }
        __syncthreads();

        // prefetch next tile
        if (k0 + BK < K) {
            int kk = k0 + BK;
#pragma unroll
            for (int q = 0; q < 4; q++) {
                int idx = tx + q * 256;
                int row = idx >> 3;
                int kq  = (idx & 7) * 4;
                int gm  = bm + row;
                pa[q] = (gm < M) ? *(const float4*)&A[(size_t)gm * K + kk + kq] : z4;
            }
#pragma unroll
            for (int q = 0; q < 2; q++) {
                int idx = tx + q * 256;
                int row = idx >> 4;
                int col = (idx & 15) * 4;
                pb[q] = *(const float4*)&B[(size_t)(kk + row) * N + bn + col];
            }
        }

        // 4 k-steps of 8
#pragma unroll
        for (int ks = 0; ks < 4; ks++) {
            int kb = ks * 8;
            uint32_t af[2][4];
#pragma unroll
            for (int mt = 0; mt < 2; mt++) {
                int r = wm + mt * 16 + gid;
                af[mt][0] = __float_as_uint(As[kb + tig][r]);
                af[mt][1] = __float_as_uint(As[kb + tig][r + 8]);
                af[mt][2] = __float_as_uint(As[kb + tig + 4][r]);
                af[mt][3] = __float_as_uint(As[kb + tig + 4][r + 8]);
            }
#pragma unroll
            for (int nt = 0; nt < 4; nt++) {
                int c = wn + nt * 8 + gid;
                uint32_t b0 = __float_as_uint(Bs[kb + tig][c]);
                uint32_t b1 = __float_as_uint(Bs[kb + tig + 4][c]);
                mma_tf32(acc[0][nt], af[0], b0, b1);
                mma_tf32(acc[1][nt], af[1], b0, b1);
            }
        }
        __syncthreads();
    }

    // epilogue
#pragma unroll
    for (int mt = 0; mt < 2; mt++) {
#pragma unroll
        for (int half = 0; half < 2; half++) {
            int m = bm + wm + mt * 16 + gid + half * 8;
            if (m >= M) continue;
#pragma unroll
            for (int nt = 0; nt < 4; nt++) {
                int n = bn + wn + nt * 8 + 2 * tig;
                float v0 = acc[mt][nt][half * 2 + 0];
                float v1 = acc[mt][nt][half * 2 + 1];
                if (mode == 1) {
                    v0 += bias[n];
                    v1 += bias[n + 1];
                    v0 = v0 > 0.f ? v0 : expm1f(v0);
                    v1 = v1 > 0.f ? v1 : expm1f(v1);
                    *(float2*)&C[(size_t)m * N + n] = make_float2(v0, v1);
                } else {
                    *(__nv_bfloat162*)&Cb[(size_t)m * N + n] = __floats2bfloat162_rn(v0, v1);
                }
            }
        }
    }
}

// ---------------- attention logits: e_src / e_dst (bf16 features) ----------
__device__ __forceinline__ float2 b2f(uint32_t u) {
    __nv_bfloat162 h;
    *reinterpret_cast<uint32_t*>(&h) = u;
    return __bfloat1622float2(h);
}

template <int H, int D>
__global__ void compute_e_kernel(const __nv_bfloat16* __restrict__ xf,
                                 const float* __restrict__ a_s,
                                 const float* __restrict__ a_d) {
    constexpr int F = H * D;
    constexpr int FP = F / 32;
    int gw = (blockIdx.x * blockDim.x + threadIdx.x) >> 5;
    int lane = threadIdx.x & 31;
    if (gw >= N_NODES) return;
    const __nv_bfloat16* xr = xf + (size_t)gw * F;
    float ps = 0.f, pd = 0.f;
    if constexpr (FP == 8) {
        uint4 r = ((const uint4*)xr)[lane];
        float2 f0 = b2f(r.x), f1 = b2f(r.y), f2 = b2f(r.z), f3 = b2f(r.w);
        float vv[8] = {f0.x, f0.y, f1.x, f1.y, f2.x, f2.y, f3.x, f3.y};
#pragma unroll
        for (int q = 0; q < 8; q++) {
            int f = lane * 8 + q;
            ps += vv[q] * a_s[f];
            pd += vv[q] * a_d[f];
        }
    } else {
        uint32_t r = ((const uint32_t*)xr)[lane];
        float2 f = b2f(r);
        int f0 = lane * 2;
        ps += f.x * a_s[f0] + f.y * a_s[f0 + 1];
        pd += f.x * a_d[f0] + f.y * a_d[f0 + 1];
    }
    constexpr int G = 32 / H;  // lanes per head
#pragma unroll
    for (int off = G >> 1; off; off >>= 1) {
        ps += __shfl_down_sync(0xffffffffu, ps, off);
        pd += __shfl_down_sync(0xffffffffu, pd, off);
    }
    if ((lane & (G - 1)) == 0) {
        int h = lane / G;
        g_esrc[gw * H + h] = ps;
        g_edst[gw * H + h] = pd;
    }
}

// ---------------- GAT aggregation: warp per destination node (bf16 xf) -----
template <int H, int D>
__global__ void gat_agg_kernel(const __nv_bfloat16* __restrict__ xf,
                               const float* __restrict__ bias,
                               float* __restrict__ out) {
    constexpr int F = H * D;
    constexpr int FP = F / 32;       // features per lane (8 or 2)
    int gw = (blockIdx.x * blockDim.x + threadIdx.x) >> 5;
    int lane = threadIdx.x & 31;
    if (gw >= N_NODES) return;
    const int i = gw;
    const int beg = g_offsets[i], end = g_offsets[i + 1];

    float edst_i[H], eself[H], m[H];
#pragma unroll
    for (int h = 0; h < H; h++) {
        edst_i[h] = g_edst[i * H + h];
        float v = g_esrc[i * H + h] + edst_i[h];
        v = v > 0.f ? v : 0.2f * v;
        eself[h] = v;
        m[h] = v;  // self-loop participates in max
    }
    // pass 1: segment max over incoming edges (scalar logits only)
    for (int k = beg + lane; k < end; k += 32) {
        int s = g_csr[k];
#pragma unroll
        for (int h = 0; h < H; h++) {
            float v = g_esrc[s * H + h] + edst_i[h];
            v = v > 0.f ? v : 0.2f * v;
            m[h] = fmaxf(m[h], v);
        }
    }
#pragma unroll
    for (int h = 0; h < H; h++)
#pragma unroll
        for (int off = 16; off; off >>= 1)
            m[h] = fmaxf(m[h], __shfl_xor_sync(0xffffffffu, m[h], off));

    // pass 2: exp-weights, running sum, warp-cooperative bf16 feature gather
    float acc[FP];
#pragma unroll
    for (int q = 0; q < FP; q++) acc[q] = 0.f;
    float ssum[H];
#pragma unroll
    for (int h = 0; h < H; h++) ssum[h] = 0.f;
    const int myh = (lane * FP) / D;

    for (int base = beg; base < end; base += 32) {
        int k = base + lane;
        int cnt = min(32, end - base);
        int s = 0;
        float w[H];
#pragma unroll
        for (int h = 0; h < H; h++) w[h] = 0.f;
        if (k < end) {
            s = g_csr[k];
#pragma unroll
            for (int h = 0; h < H; h++) {
                float v = g_esrc[s * H + h] + edst_i[h];
                v = v > 0.f ? v : 0.2f * v;
                float ww = __expf(v - m[h]);
                w[h] = ww;
                ssum[h] += ww;
            }
        }
        for (int j = 0; j < cnt; j++) {
            int sj = __shfl_sync(0xffffffffu, s, j);
            float wh;
            if constexpr (H == 4) {
                float w0 = __shfl_sync(0xffffffffu, w[0], j);
                float w1 = __shfl_sync(0xffffffffu, w[1], j);
                float w2 = __shfl_sync(0xffffffffu, w[2], j);
                float w3 = __shfl_sync(0xffffffffu, w[3], j);
                wh = (myh == 0) ? w0 : (myh == 1) ? w1 : (myh == 2) ? w2 : w3;
            } else {
                wh = __shfl_sync(0xffffffffu, w[0], j);
            }
            const __nv_bfloat16* xr = xf + (size_t)sj * F;
            if constexpr (FP == 8) {
                uint4 r = ((const uint4*)xr)[lane];
                float2 f0 = b2f(r.x), f1 = b2f(r.y), f2 = b2f(r.z), f3 = b2f(r.w);
                acc[0] += wh * f0.x; acc[1] += wh * f0.y;
                acc[2] += wh * f1.x; acc[3] += wh * f1.y;
                acc[4] += wh * f2.x; acc[5] += wh * f2.y;
                acc[6] += wh * f3.x; acc[7] += wh * f3.y;
            } else {
                uint32_t r = ((const uint32_t*)xr)[lane];
                float2 f = b2f(r);
                acc[0] += wh * f.x; acc[1] += wh * f.y;
            }
        }
    }
    // total exp-sum across the warp, then fold in self-loop
#pragma unroll
    for (int h = 0; h < H; h++)
#pragma unroll
        for (int off = 16; off; off >>= 1)
            ssum[h] += __shfl_xor_sync(0xffffffffu, ssum[h], off);
    float wself[H];
#pragma unroll
    for (int h = 0; h < H; h++) {
        wself[h] = __expf(eself[h] - m[h]);
        ssum[h] += wself[h];
    }
    {
        float wh;
        if constexpr (H == 4)
            wh = (myh == 0) ? wself[0] : (myh == 1) ? wself[1] : (myh == 2) ? wself[2] : wself[3];
        else
            wh = wself[0];
        const __nv_bfloat16* xr = xf + (size_t)i * F;
        if constexpr (FP == 8) {
            uint4 r = ((const uint4*)xr)[lane];
            float2 f0 = b2f(r.x), f1 = b2f(r.y), f2 = b2f(r.z), f3 = b2f(r.w);
            acc[0] += wh * f0.x; acc[1] += wh * f0.y;
            acc[2] += wh * f1.x; acc[3] += wh * f1.y;
            acc[4] += wh * f2.x; acc[5] += wh * f2.y;
            acc[6] += wh * f3.x; acc[7] += wh * f3.y;
        } else {
            uint32_t r = ((const uint32_t*)xr)[lane];
            float2 f = b2f(r);
            acc[0] += wh * f.x; acc[1] += wh * f.y;
        }
    }
    float denom;
    if constexpr (H == 4)
        denom = (myh == 0) ? ssum[0] : (myh == 1) ? ssum[1] : (myh == 2) ? ssum[2] : ssum[3];
    else
        denom = ssum[0];
    float inv = 1.f / denom;
#pragma unroll
    for (int q = 0; q < FP; q++) {
        int f = lane * FP + q;
        float v = acc[q] * inv + bias[f];
        v = v > 0.f ? v : expm1f(v);   // elu applied after every GAT layer
        out[(size_t)i * F + f] = v;
    }
}

// ---------------- global mean pool + output projection ---------------------
__global__ void pool_kernel(const float* __restrict__ h) {
    __shared__ float sacc[64];
    int t = threadIdx.x;
    if (t < 64) sacc[t] = 0.f;
    __syncthreads();
    int col = t & 63;
    int rpb = blockDim.x >> 6;  // rows per block pass
    float a = 0.f;
    for (int r = blockIdx.x * rpb + (t >> 6); r < N_NODES; r += gridDim.x * rpb)
        a += h[(size_t)r * 64 + col];
    atomicAdd(&sacc[col], a);
    __syncthreads();
    if (t < 64) atomicAdd(&g_pool[t], sacc[t]);
}

__global__ void final_kernel(const float* __restrict__ w_out,
                             const float* __restrict__ b_out,
                             float* __restrict__ out) {
    int j = threadIdx.x;  // 0..127
    float s = b_out[j];
    const float invn = 1.f / (float)N_NODES;
    for (int k = 0; k < 64; k++)
        s += g_pool[k] * invn * w_out[k * 128 + j];
    out[j] = s;
}

// ---------------- launcher -------------------------------------------------
extern "C" void kernel_launch(void* const* d_in, const int* in_sizes, int n_in,
                              void* d_out, int out_size) {
    const float* x     = (const float*)d_in[0];
    const int*   ei    = (const int*)d_in[1];
    const int*   src   = ei;
    const int*   dst   = ei + N_EDGES;
    const float* w_in  = (const float*)d_in[2];
    const float* b_in  = (const float*)d_in[3];
    const float* W0    = (const float*)d_in[4];
    const float* as0   = (const float*)d_in[5];
    const float* ad0   = (const float*)d_in[6];
    const float* bb0   = (const float*)d_in[7];
    const float* W1    = (const float*)d_in[8];
    const float* as1   = (const float*)d_in[9];
    const float* ad1   = (const float*)d_in[10];
    const float* bb1   = (const float*)d_in[11];
    const float* W2    = (const float*)d_in[12];
    const float* as2   = (const float*)d_in[13];
    const float* ad2   = (const float*)d_in[14];
    const float* bb2   = (const float*)d_in[15];
    const float* w_out = (const float*)d_in[16];
    const float* b_out = (const float*)d_in[17];
    float* out = (float*)d_out;

    void *p_h64, *p_xf, *p_hA, *p_hB;
    cudaGetSymbolAddress(&p_h64, g_h64);
    cudaGetSymbolAddress(&p_xf,  g_xf);
    cudaGetSymbolAddress(&p_hA,  g_hA);
    cudaGetSymbolAddress(&p_hB,  g_hB);
    float* h64 = (float*)p_h64;
    __nv_bfloat16* xf = (__nv_bfloat16*)p_xf;
    float* hA  = (float*)p_hA;
    float* hB  = (float*)p_hB;

    const int EB = (N_EDGES + 255) / 256;
    const int NB = (N_NODES + 255) / 256;
    const int MY = (N_NODES + 127) / 128;   // 391 row-blocks of 128
    const int WARPB = N_NODES / 8;          // 6250 blocks of 8 warps

    // CSR build (per-launch; deterministic workload)
    zero_kernel<<<NB, 256>>>();
    hist_kernel<<<EB, 256>>>(dst);
    scan_kernel<<<1, 1024>>>();
    scatter_kernel<<<EB, 256>>>(src, dst);

    // input MLP: h64 = elu(x @ w_in + b_in)   (fp32 out)
    tf32gemm_kernel<<<dim3(1, MY), 256>>>(x, w_in, b_in, h64, nullptr,
                                          N_NODES, 64, 256, 1);

    // GAT layer 0 (H=4, D=64): GEMM -> bf16 xf, then e-logits, then agg
    tf32gemm_kernel<<<dim3(4, MY), 256>>>(h64, W0, nullptr, nullptr, xf,
                                          N_NODES, 256, 64, 0);
    compute_e_kernel<4, 64><<<WARPB, 256>>>(xf, as0, ad0);
    gat_agg_kernel<4, 64><<<WARPB, 256>>>(xf, bb0, hA);

    // GAT layer 1 (H=4, D=64)
    tf32gemm_kernel<<<dim3(4, MY), 256>>>(hA, W1, nullptr, nullptr, xf,
                                          N_NODES, 256, 256, 0);
    compute_e_kernel<4, 64><<<WARPB, 256>>>(xf, as1, ad1);
    gat_agg_kernel<4, 64><<<WARPB, 256>>>(xf, bb1, hB);

    // GAT layer 2 (H=1, D=64)
    tf32gemm_kernel<<<dim3(1, MY), 256>>>(hB, W2, nullptr, nullptr, xf,
                                          N_NODES, 64, 256, 0);
    compute_e_kernel<1, 64><<<WARPB, 256>>>(xf, as2, ad2);
    gat_agg_kernel<1, 64><<<WARPB, 256>>>(xf, bb2, h64);

    // global mean pool + out projection
    pool_kernel<<<256, 256>>>(h64);
    final_kernel<<<1, 128>>>(w_out, b_out, out);
}

// round 12
// speedup vs baseline: 1.4942x; 1.0517x over previous
#include <cuda_runtime.h>
#include <cuda_bf16.h>
#include <math.h>
#include <stdint.h>

#define N_NODES 50000
#define N_EDGES 800000

__device__ int   g_counts[N_NODES];
__device__ int   g_offsets[N_NODES + 1];
__device__ int   g_cursor[N_NODES];
__device__ int   g_csr[N_EDGES];
__device__ float g_h64[(size_t)N_NODES * 64];
__device__ __nv_bfloat16 g_xf[(size_t)N_NODES * 256];
__device__ float g_hA [(size_t)N_NODES * 256];
__device__ float g_hB [(size_t)N_NODES * 256];
__device__ float g_esrc[N_NODES * 4];
__device__ float g_edst[N_NODES * 4];
__device__ float g_pool[64];

// ---------------- CSR build ------------------------------------------------
__global__ void zero_kernel() {
    int i = blockIdx.x * blockDim.x + threadIdx.x;
    if (i < N_NODES) g_counts[i] = 0;
    if (i < 64) g_pool[i] = 0.f;
}

__global__ void hist_kernel(const int* __restrict__ dst) {
    int i = blockIdx.x * blockDim.x + threadIdx.x;
    if (i < N_EDGES) atomicAdd(&g_counts[dst[i]], 1);
}

__global__ void scan_kernel() {
    __shared__ int ssum[1024];
    int t = threadIdx.x;
    const int CH = (N_NODES + 1023) / 1024;
    int base = t * CH;
    int s = 0;
    for (int c = 0; c < CH; c++) {
        int idx = base + c;
        if (idx < N_NODES) s += g_counts[idx];
    }
    ssum[t] = s;
    __syncthreads();
    for (int off = 1; off < 1024; off <<= 1) {
        int v = (t >= off) ? ssum[t - off] : 0;
        __syncthreads();
        ssum[t] += v;
        __syncthreads();
    }
    int run = (t == 0) ? 0 : ssum[t - 1];
    for (int c = 0; c < CH; c++) {
        int idx = base + c;
        if (idx < N_NODES) {
            g_offsets[idx] = run;
            g_cursor[idx]  = run;
            run += g_counts[idx];
        }
    }
    if (t == 1023) g_offsets[N_NODES] = ssum[1023];
}

__global__ void scatter_kernel(const int* __restrict__ src, const int* __restrict__ dst) {
    int i = blockIdx.x * blockDim.x + threadIdx.x;
    if (i < N_EDGES) {
        int p = atomicAdd(&g_cursor[dst[i]], 1);
        g_csr[p] = src[i];
    }
}

// ---------------- TF32 tensor-core GEMM (exact R2 structure) ----------------
__device__ __forceinline__ float tf32r(float x) {
    float y;
    asm("cvt.rna.tf32.f32 %0, %1;" : "=f"(y) : "f"(x));
    return y;
}

__device__ __forceinline__ void mma_tf32(float* c, const uint32_t* a, uint32_t b0, uint32_t b1) {
    asm volatile(
        "mma.sync.aligned.m16n8k8.row.col.f32.tf32.tf32.f32 "
        "{%0,%1,%2,%3},{%4,%5,%6,%7},{%8,%9},{%0,%1,%2,%3};"
        : "+f"(c[0]), "+f"(c[1]), "+f"(c[2]), "+f"(c[3])
        : "r"(a[0]), "r"(a[1]), "r"(a[2]), "r"(a[3]), "r"(b0), "r"(b1));
}

__global__ __launch_bounds__(256) void tf32gemm_kernel(
        const float* __restrict__ A, const float* __restrict__ B,
        const float* __restrict__ bias, float* __restrict__ C,
        __nv_bfloat16* __restrict__ Cb,
        int M, int N, int K, int mode) {
    const int BM = 128, BN = 64, BK = 32;
    __shared__ float As[BK][BM + 4];
    __shared__ float Bs[BK][BN + 4];
    int tx = threadIdx.x;
    int bm = blockIdx.y * BM;
    int bn = blockIdx.x * BN;
    int wid = tx >> 5, lane = tx & 31;
    int wm = (wid >> 1) * 32;
    int wn = (wid & 1) * 32;
    const int gid = lane >> 2;
    const int tig = lane & 3;

    float acc[2][4][4];
#pragma unroll
    for (int mt = 0; mt < 2; mt++)
#pragma unroll
        for (int nt = 0; nt < 4; nt++)
#pragma unroll
            for (int q = 0; q < 4; q++) acc[mt][nt][q] = 0.f;

    const float4 z4 = make_float4(0.f, 0.f, 0.f, 0.f);
    float4 pa[4], pb[2];

#pragma unroll
    for (int q = 0; q < 4; q++) {
        int idx = tx + q * 256;
        int row = idx >> 3;
        int kq  = (idx & 7) * 4;
        int gm  = bm + row;
        pa[q] = (gm < M) ? *(const float4*)&A[(size_t)gm * K + kq] : z4;
    }
#pragma unroll
    for (int q = 0; q < 2; q++) {
        int idx = tx + q * 256;
        int row = idx >> 4;
        int col = (idx & 15) * 4;
        pb[q] = *(const float4*)&B[(size_t)row * N + bn + col];
    }

    for (int k0 = 0; k0 < K; k0 += BK) {
#pragma unroll
        for (int q = 0; q < 4; q++) {
            int idx = tx + q * 256;
            int row = idx >> 3;
            int kq  = (idx & 7) * 4;
            As[kq + 0][row] = tf32r(pa[q].x);
            As[kq + 1][row] = tf32r(pa[q].y);
            As[kq + 2][row] = tf32r(pa[q].z);
            As[kq + 3][row] = tf32r(pa[q].w);
        }
#pragma unroll
        for (int q = 0; q < 2; q++) {
            int idx = tx + q * 256;
            int row = idx >> 4;
            int col = (idx & 15) * 4;
            Bs[row][col + 0] = tf32r(pb[q].x);
            Bs[row][col + 1] = tf32r(pb[q].y);
            Bs[row][col + 2] = tf32r(pb[q].z);
            Bs[row][col + 3] = tf32r(pb[q].w);
        }
        __syncthreads();

        if (k0 + BK < K) {
            int kk = k0 + BK;
#pragma unroll
            for (int q = 0; q < 4; q++) {
                int idx = tx + q * 256;
                int row = idx >> 3;
                int kq  = (idx & 7) * 4;
                int gm  = bm + row;
                pa[q] = (gm < M) ? *(const float4*)&A[(size_t)gm * K + kk + kq] : z4;
            }
#pragma unroll
            for (int q = 0; q < 2; q++) {
                int idx = tx + q * 256;
                int row = idx >> 4;
                int col = (idx & 15) * 4;
                pb[q] = *(const float4*)&B[(size_t)(kk + row) * N + bn + col];
            }
        }

#pragma unroll
        for (int ks = 0; ks < 4; ks++) {
            int kb = ks * 8;
            uint32_t af[2][4];
#pragma unroll
            for (int mt = 0; mt < 2; mt++) {
                int r = wm + mt * 16 + gid;
                af[mt][0] = __float_as_uint(As[kb + tig][r]);
                af[mt][1] = __float_as_uint(As[kb + tig][r + 8]);
                af[mt][2] = __float_as_uint(As[kb + tig + 4][r]);
                af[mt][3] = __float_as_uint(As[kb + tig + 4][r + 8]);
            }
#pragma unroll
            for (int nt = 0; nt < 4; nt++) {
                int c = wn + nt * 8 + gid;
                uint32_t b0 = __float_as_uint(Bs[kb + tig][c]);
                uint32_t b1 = __float_as_uint(Bs[kb + tig + 4][c]);
                mma_tf32(acc[0][nt], af[0], b0, b1);
                mma_tf32(acc[1][nt], af[1], b0, b1);
            }
        }
        __syncthreads();
    }

#pragma unroll
    for (int mt = 0; mt < 2; mt++) {
#pragma unroll
        for (int half = 0; half < 2; half++) {
            int m = bm + wm + mt * 16 + gid + half * 8;
            if (m >= M) continue;
#pragma unroll
            for (int nt = 0; nt < 4; nt++) {
                int n = bn + wn + nt * 8 + 2 * tig;
                float v0 = acc[mt][nt][half * 2 + 0];
                float v1 = acc[mt][nt][half * 2 + 1];
                if (mode == 1) {
                    v0 += bias[n];
                    v1 += bias[n + 1];
                    v0 = v0 > 0.f ? v0 : expm1f(v0);
                    v1 = v1 > 0.f ? v1 : expm1f(v1);
                    *(float2*)&C[(size_t)m * N + n] = make_float2(v0, v1);
                } else {
                    *(__nv_bfloat162*)&Cb[(size_t)m * N + n] = __floats2bfloat162_rn(v0, v1);
                }
            }
        }
    }
}

// ---------------- attention logits: e_src / e_dst (bf16 features) ----------
__device__ __forceinline__ float2 b2f(uint32_t u) {
    __nv_bfloat162 h;
    *reinterpret_cast<uint32_t*>(&h) = u;
    return __bfloat1622float2(h);
}

template <int H, int D>
__global__ void compute_e_kernel(const __nv_bfloat16* __restrict__ xf,
                                 const float* __restrict__ a_s,
                                 const float* __restrict__ a_d) {
    constexpr int F = H * D;
    constexpr int FP = F / 32;
    int gw = (blockIdx.x * blockDim.x + threadIdx.x) >> 5;
    int lane = threadIdx.x & 31;
    if (gw >= N_NODES) return;
    const __nv_bfloat16* xr = xf + (size_t)gw * F;
    float ps = 0.f, pd = 0.f;
    if constexpr (FP == 8) {
        uint4 r = ((const uint4*)xr)[lane];
        float2 f0 = b2f(r.x), f1 = b2f(r.y), f2 = b2f(r.z), f3 = b2f(r.w);
        float vv[8] = {f0.x, f0.y, f1.x, f1.y, f2.x, f2.y, f3.x, f3.y};
#pragma unroll
        for (int q = 0; q < 8; q++) {
            int f = lane * 8 + q;
            ps += vv[q] * a_s[f];
            pd += vv[q] * a_d[f];
        }
    } else {
        uint32_t r = ((const uint32_t*)xr)[lane];
        float2 f = b2f(r);
        int f0 = lane * 2;
        ps += f.x * a_s[f0] + f.y * a_s[f0 + 1];
        pd += f.x * a_d[f0] + f.y * a_d[f0 + 1];
    }
    constexpr int G = 32 / H;
#pragma unroll
    for (int off = G >> 1; off; off >>= 1) {
        ps += __shfl_down_sync(0xffffffffu, ps, off);
        pd += __shfl_down_sync(0xffffffffu, pd, off);
    }
    if ((lane & (G - 1)) == 0) {
        int h = lane / G;
        g_esrc[gw * H + h] = ps;
        g_edst[gw * H + h] = pd;
    }
}

// ---------------- GAT aggregation (no max-shift, smem-staged, pipelined) ---
template <int H, int D>
__global__ __launch_bounds__(256) void gat_agg_kernel(
        const __nv_bfloat16* __restrict__ xf,
        const float* __restrict__ bias,
        float* __restrict__ out) {
    constexpr int F = H * D;
    constexpr int FP = F / 32;       // features per lane (8 or 2)
    __shared__ float swv[8][32][H];
    __shared__ int   ssc[8][32];

    int wslot = threadIdx.x >> 5;
    int gw = (blockIdx.x * blockDim.x + threadIdx.x) >> 5;
    int lane = threadIdx.x & 31;
    if (gw >= N_NODES) return;
    const int i = gw;
    const int beg = g_offsets[i], end = g_offsets[i + 1];

    float edst_i[H], wself[H];
#pragma unroll
    for (int h = 0; h < H; h++) {
        edst_i[h] = g_edst[i * H + h];
        float v = g_esrc[i * H + h] + edst_i[h];
        v = v > 0.f ? v : 0.2f * v;
        wself[h] = __expf(v);
    }

    float acc[FP];
#pragma unroll
    for (int q = 0; q < FP; q++) acc[q] = 0.f;
    float ssum[H];
#pragma unroll
    for (int h = 0; h < H; h++) ssum[h] = 0.f;
    const int myh = (lane * FP) / D;

    for (int base = beg; base < end; base += 32) {
        int k = base + lane;
        int cnt = min(32, end - base);
        if (k < end) {
            int s = g_csr[k];
            ssc[wslot][lane] = s;
            float wv[H];
#pragma unroll
            for (int h = 0; h < H; h++) {
                float v = g_esrc[s * H + h] + edst_i[h];
                v = v > 0.f ? v : 0.2f * v;
                float ww = __expf(v);
                wv[h] = ww;
                ssum[h] += ww;
            }
            if constexpr (H == 4)
                *(float4*)&swv[wslot][lane][0] = make_float4(wv[0], wv[1], wv[2], wv[3]);
            else
                swv[wslot][lane][0] = wv[0];
        }
        __syncwarp();

        if constexpr (FP == 8) {
            // lane owns 8 features (one uint4 of bf16): feat lane*8 .. lane*8+7
            uint4 cur;
            {
                int s0 = ssc[wslot][0];
                cur = ((const uint4*)(xf + (size_t)s0 * F))[lane];
            }
            for (int j = 0; j < cnt; j++) {
                float wh = swv[wslot][j][myh];
                uint4 nxt = cur;
                if (j + 1 < cnt) {
                    int sn = ssc[wslot][j + 1];
                    nxt = ((const uint4*)(xf + (size_t)sn * F))[lane];
                }
                float2 f0 = b2f(cur.x), f1 = b2f(cur.y), f2 = b2f(cur.z), f3 = b2f(cur.w);
                acc[0] += wh * f0.x; acc[1] += wh * f0.y;
                acc[2] += wh * f1.x; acc[3] += wh * f1.y;
                acc[4] += wh * f2.x; acc[5] += wh * f2.y;
                acc[6] += wh * f3.x; acc[7] += wh * f3.y;
                cur = nxt;
            }
        } else {
            uint32_t cur;
            {
                int s0 = ssc[wslot][0];
                cur = ((const uint32_t*)(xf + (size_t)s0 * F))[lane];
            }
            for (int j = 0; j < cnt; j++) {
                float wh = swv[wslot][j][0];
                uint32_t nxt = cur;
                if (j + 1 < cnt) {
                    int sn = ssc[wslot][j + 1];
                    nxt = ((const uint32_t*)(xf + (size_t)sn * F))[lane];
                }
                float2 f = b2f(cur);
                acc[0] += wh * f.x; acc[1] += wh * f.y;
                cur = nxt;
            }
        }
        __syncwarp();
    }

#pragma unroll
    for (int h = 0; h < H; h++)
#pragma unroll
        for (int off = 16; off; off >>= 1)
            ssum[h] += __shfl_xor_sync(0xffffffffu, ssum[h], off);
#pragma unroll
    for (int h = 0; h < H; h++) ssum[h] += wself[h];

    {
        float wh;
        if constexpr (H == 4)
            wh = (myh == 0) ? wself[0] : (myh == 1) ? wself[1] : (myh == 2) ? wself[2] : wself[3];
        else
            wh = wself[0];
        const __nv_bfloat16* xr = xf + (size_t)i * F;
        if constexpr (FP == 8) {
            uint4 r = ((const uint4*)xr)[lane];
            float2 f0 = b2f(r.x), f1 = b2f(r.y), f2 = b2f(r.z), f3 = b2f(r.w);
            acc[0] += wh * f0.x; acc[1] += wh * f0.y;
            acc[2] += wh * f1.x; acc[3] += wh * f1.y;
            acc[4] += wh * f2.x; acc[5] += wh * f2.y;
            acc[6] += wh * f3.x; acc[7] += wh * f3.y;
        } else {
            uint32_t r = ((const uint32_t*)xr)[lane];
            float2 f = b2f(r);
            acc[0] += wh * f.x; acc[1] += wh * f.y;
        }
    }

    float denom;
    if constexpr (H == 4)
        denom = (myh == 0) ? ssum[0] : (myh == 1) ? ssum[1] : (myh == 2) ? ssum[2] : ssum[3];
    else
        denom = ssum[0];
    float inv = 1.f / denom;
#pragma unroll
    for (int q = 0; q < FP; q++) {
        int f = lane * FP + q;
        float v = acc[q] * inv + bias[f];
        v = v > 0.f ? v : expm1f(v);
        out[(size_t)i * F + f] = v;
    }
}

// ---------------- global mean pool + output projection ---------------------
__global__ void pool_kernel(const float* __restrict__ h) {
    __shared__ float sacc[64];
    int t = threadIdx.x;
    if (t < 64) sacc[t] = 0.f;
    __syncthreads();
    int col = t & 63;
    int rpb = blockDim.x >> 6;
    float a = 0.f;
    for (int r = blockIdx.x * rpb + (t >> 6); r < N_NODES; r += gridDim.x * rpb)
        a += h[(size_t)r * 64 + col];
    atomicAdd(&sacc[col], a);
    __syncthreads();
    if (t < 64) atomicAdd(&g_pool[t], sacc[t]);
}

__global__ void final_kernel(const float* __restrict__ w_out,
                             const float* __restrict__ b_out,
                             float* __restrict__ out) {
    int j = threadIdx.x;
    float s = b_out[j];
    const float invn = 1.f / (float)N_NODES;
    for (int k = 0; k < 64; k++)
        s += g_pool[k] * invn * w_out[k * 128 + j];
    out[j] = s;
}

// ---------------- launcher -------------------------------------------------
extern "C" void kernel_launch(void* const* d_in, const int* in_sizes, int n_in,
                              void* d_out, int out_size) {
    const float* x     = (const float*)d_in[0];
    const int*   ei    = (const int*)d_in[1];
    const int*   src   = ei;
    const int*   dst   = ei + N_EDGES;
    const float* w_in  = (const float*)d_in[2];
    const float* b_in  = (const float*)d_in[3];
    const float* W0    = (const float*)d_in[4];
    const float* as0   = (const float*)d_in[5];
    const float* ad0   = (const float*)d_in[6];
    const float* bb0   = (const float*)d_in[7];
    const float* W1    = (const float*)d_in[8];
    const float* as1   = (const float*)d_in[9];
    const float* ad1   = (const float*)d_in[10];
    const float* bb1   = (const float*)d_in[11];
    const float* W2    = (const float*)d_in[12];
    const float* as2   = (const float*)d_in[13];
    const float* ad2   = (const float*)d_in[14];
    const float* bb2   = (const float*)d_in[15];
    const float* w_out = (const float*)d_in[16];
    const float* b_out = (const float*)d_in[17];
    float* out = (float*)d_out;

    void *p_h64, *p_xf, *p_hA, *p_hB;
    cudaGetSymbolAddress(&p_h64, g_h64);
    cudaGetSymbolAddress(&p_xf,  g_xf);
    cudaGetSymbolAddress(&p_hA,  g_hA);
    cudaGetSymbolAddress(&p_hB,  g_hB);
    float* h64 = (float*)p_h64;
    __nv_bfloat16* xf = (__nv_bfloat16*)p_xf;
    float* hA  = (float*)p_hA;
    float* hB  = (float*)p_hB;

    const int EB = (N_EDGES + 255) / 256;
    const int NB = (N_NODES + 255) / 256;
    const int MY = (N_NODES + 127) / 128;
    const int WARPB = N_NODES / 8;

    zero_kernel<<<NB, 256>>>();
    hist_kernel<<<EB, 256>>>(dst);
    scan_kernel<<<1, 1024>>>();
    scatter_kernel<<<EB, 256>>>(src, dst);

    tf32gemm_kernel<<<dim3(1, MY), 256>>>(x, w_in, b_in, h64, nullptr,
                                          N_NODES, 64, 256, 1);

    tf32gemm_kernel<<<dim3(4, MY), 256>>>(h64, W0, nullptr, nullptr, xf,
                                          N_NODES, 256, 64, 0);
    compute_e_kernel<4, 64><<<WARPB, 256>>>(xf, as0, ad0);
    gat_agg_kernel<4, 64><<<WARPB, 256>>>(xf, bb0, hA);

    tf32gemm_kernel<<<dim3(4, MY), 256>>>(hA, W1, nullptr, nullptr, xf,
                                          N_NODES, 256, 256, 0);
    compute_e_kernel<4, 64><<<WARPB, 256>>>(xf, as1, ad1);
    gat_agg_kernel<4, 64><<<WARPB, 256>>>(xf, bb1, hB);

    tf32gemm_kernel<<<dim3(1, MY), 256>>>(hB, W2, nullptr, nullptr, xf,
                                          N_NODES, 64, 256, 0);
    compute_e_kernel<1, 64><<<WARPB, 256>>>(xf, as2, ad2);
    gat_agg_kernel<1, 64><<<WARPB, 256>>>(xf, bb2, h64);

    pool_kernel<<<256, 256>>>(h64);
    final_kernel<<<1, 128>>>(w_out, b_out, out);
}

// round 13
// speedup vs baseline: 1.5531x; 1.0394x over previous
#include <cuda_runtime.h>
#include <cuda_bf16.h>
#include <math.h>
#include <stdint.h>

#define N_NODES 50000
#define N_EDGES 800000

__device__ int   g_counts[N_NODES];
__device__ int   g_offsets[N_NODES + 1];
__device__ int   g_cursor[N_NODES];
__device__ int   g_csr[N_EDGES];
__device__ float g_h64[(size_t)N_NODES * 64];
__device__ __nv_bfloat16 g_xf[(size_t)N_NODES * 256];
__device__ float g_hA [(size_t)N_NODES * 256];
__device__ float g_hB [(size_t)N_NODES * 256];
__device__ float g_esrc[N_NODES * 4];
__device__ float g_edst[N_NODES * 4];
__device__ float g_pool[64];

// ---------------- CSR build ------------------------------------------------
__global__ void zero_kernel() {
    int i = blockIdx.x * blockDim.x + threadIdx.x;
    if (i < N_NODES) g_counts[i] = 0;
    if (i < 64) g_pool[i] = 0.f;
}

__global__ void hist_kernel(const int* __restrict__ dst) {
    int i = blockIdx.x * blockDim.x + threadIdx.x;
    if (i < N_EDGES) atomicAdd(&g_counts[dst[i]], 1);
}

__global__ void scan_kernel() {
    __shared__ int ssum[1024];
    int t = threadIdx.x;
    const int CH = (N_NODES + 1023) / 1024;
    int base = t * CH;
    int s = 0;
    for (int c = 0; c < CH; c++) {
        int idx = base + c;
        if (idx < N_NODES) s += g_counts[idx];
    }
    ssum[t] = s;
    __syncthreads();
    for (int off = 1; off < 1024; off <<= 1) {
        int v = (t >= off) ? ssum[t - off] : 0;
        __syncthreads();
        ssum[t] += v;
        __syncthreads();
    }
    int run = (t == 0) ? 0 : ssum[t - 1];
    for (int c = 0; c < CH; c++) {
        int idx = base + c;
        if (idx < N_NODES) {
            g_offsets[idx] = run;
            g_cursor[idx]  = run;
            run += g_counts[idx];
        }
    }
    if (t == 1023) g_offsets[N_NODES] = ssum[1023];
}

__global__ void scatter_kernel(const int* __restrict__ src, const int* __restrict__ dst) {
    int i = blockIdx.x * blockDim.x + threadIdx.x;
    if (i < N_EDGES) {
        int p = atomicAdd(&g_cursor[dst[i]], 1);
        g_csr[p] = src[i];
    }
}

// ---------------- TF32 tensor-core GEMM, double-buffered smem ---------------
// mode 0: plain bf16 store to Cb; mode 1: fp32 store +bias+elu.
__device__ __forceinline__ float tf32r(float x) {
    float y;
    asm("cvt.rna.tf32.f32 %0, %1;" : "=f"(y) : "f"(x));
    return y;
}

__device__ __forceinline__ void mma_tf32(float* c, const uint32_t* a, uint32_t b0, uint32_t b1) {
    asm volatile(
        "mma.sync.aligned.m16n8k8.row.col.f32.tf32.tf32.f32 "
        "{%0,%1,%2,%3},{%4,%5,%6,%7},{%8,%9},{%0,%1,%2,%3};"
        : "+f"(c[0]), "+f"(c[1]), "+f"(c[2]), "+f"(c[3])
        : "r"(a[0]), "r"(a[1]), "r"(a[2]), "r"(a[3]), "r"(b0), "r"(b1));
}

__global__ __launch_bounds__(256) void tf32gemm_kernel(
        const float* __restrict__ A, const float* __restrict__ B,
        const float* __restrict__ bias, float* __restrict__ C,
        __nv_bfloat16* __restrict__ Cb,
        int M, int N, int K, int mode) {
    const int BM = 128, BN = 64, BK = 32;
    __shared__ float As[2][BK][BM + 4];
    __shared__ float Bs[2][BK][BN + 4];
    int tx = threadIdx.x;
    int bm = blockIdx.y * BM;
    int bn = blockIdx.x * BN;
    int wid = tx >> 5, lane = tx & 31;
    int wm = (wid >> 1) * 32;
    int wn = (wid & 1) * 32;
    const int gid = lane >> 2;
    const int tig = lane & 3;

    float acc[2][4][4];
#pragma unroll
    for (int mt = 0; mt < 2; mt++)
#pragma unroll
        for (int nt = 0; nt < 4; nt++)
#pragma unroll
            for (int q = 0; q < 4; q++) acc[mt][nt][q] = 0.f;

    const float4 z4 = make_float4(0.f, 0.f, 0.f, 0.f);
    float4 pa[4], pb[2];

    // A-load map: idx = tx + q*256 -> row = idx>>3 (0..127), kq = (idx&7)*4
    // B-load map: idx = tx + q*256 -> br  = idx>>4 (0..31),  bc = (idx&15)*4
#pragma unroll
    for (int q = 0; q < 4; q++) {
        int idx = tx + q * 256;
        int row = idx >> 3, kq = (idx & 7) * 4;
        int gm = bm + row;
        pa[q] = (gm < M) ? *(const float4*)&A[(size_t)gm * K + kq] : z4;
    }
#pragma unroll
    for (int q = 0; q < 2; q++) {
        int idx = tx + q * 256;
        int br = idx >> 4, bc = (idx & 15) * 4;
        pb[q] = *(const float4*)&B[(size_t)br * N + bn + bc];
    }

    // commit tile 0 into buffer 0
#pragma unroll
    for (int q = 0; q < 4; q++) {
        int idx = tx + q * 256;
        int row = idx >> 3, kq = (idx & 7) * 4;
        As[0][kq + 0][row] = tf32r(pa[q].x);
        As[0][kq + 1][row] = tf32r(pa[q].y);
        As[0][kq + 2][row] = tf32r(pa[q].z);
        As[0][kq + 3][row] = tf32r(pa[q].w);
    }
#pragma unroll
    for (int q = 0; q < 2; q++) {
        int idx = tx + q * 256;
        int br = idx >> 4, bc = (idx & 15) * 4;
        Bs[0][br][bc + 0] = tf32r(pb[q].x);
        Bs[0][br][bc + 1] = tf32r(pb[q].y);
        Bs[0][br][bc + 2] = tf32r(pb[q].z);
        Bs[0][br][bc + 3] = tf32r(pb[q].w);
    }
    __syncthreads();

    const int NT = K / BK;
    for (int t = 0; t < NT; t++) {
        int cur = t & 1;
        bool has_next = (t + 1 < NT);

        // prefetch next tile into registers (global)
        if (has_next) {
            int kk = (t + 1) * BK;
#pragma unroll
            for (int q = 0; q < 4; q++) {
                int idx = tx + q * 256;
                int row = idx >> 3, kq = (idx & 7) * 4;
                int gm = bm + row;
                pa[q] = (gm < M) ? *(const float4*)&A[(size_t)gm * K + kk + kq] : z4;
            }
#pragma unroll
            for (int q = 0; q < 2; q++) {
                int idx = tx + q * 256;
                int br = idx >> 4, bc = (idx & 15) * 4;
                pb[q] = *(const float4*)&B[(size_t)(kk + br) * N + bn + bc];
            }
        }

        // compute from current buffer
#pragma unroll
        for (int ks = 0; ks < 4; ks++) {
            int kb = ks * 8;
            uint32_t af[2][4];
#pragma unroll
            for (int mt = 0; mt < 2; mt++) {
                int r = wm + mt * 16 + gid;
                af[mt][0] = __float_as_uint(As[cur][kb + tig][r]);
                af[mt][1] = __float_as_uint(As[cur][kb + tig][r + 8]);
                af[mt][2] = __float_as_uint(As[cur][kb + tig + 4][r]);
                af[mt][3] = __float_as_uint(As[cur][kb + tig + 4][r + 8]);
            }
#pragma unroll
            for (int nt = 0; nt < 4; nt++) {
                int c = wn + nt * 8 + gid;
                uint32_t b0 = __float_as_uint(Bs[cur][kb + tig][c]);
                uint32_t b1 = __float_as_uint(Bs[cur][kb + tig + 4][c]);
                mma_tf32(acc[0][nt], af[0], b0, b1);
                mma_tf32(acc[1][nt], af[1], b0, b1);
            }
        }

        // commit next tile into the alternate buffer (consumed last iter)
        if (has_next) {
            int nxt = cur ^ 1;
#pragma unroll
            for (int q = 0; q < 4; q++) {
                int idx = tx + q * 256;
                int row = idx >> 3, kq = (idx & 7) * 4;
                As[nxt][kq + 0][row] = tf32r(pa[q].x);
                As[nxt][kq + 1][row] = tf32r(pa[q].y);
                As[nxt][kq + 2][row] = tf32r(pa[q].z);
                As[nxt][kq + 3][row] = tf32r(pa[q].w);
            }
#pragma unroll
            for (int q = 0; q < 2; q++) {
                int idx = tx + q * 256;
                int br = idx >> 4, bc = (idx & 15) * 4;
                Bs[nxt][br][bc + 0] = tf32r(pb[q].x);
                Bs[nxt][br][bc + 1] = tf32r(pb[q].y);
                Bs[nxt][br][bc + 2] = tf32r(pb[q].z);
                Bs[nxt][br][bc + 3] = tf32r(pb[q].w);
            }
        }
        __syncthreads();
    }

#pragma unroll
    for (int mt = 0; mt < 2; mt++) {
#pragma unroll
        for (int half = 0; half < 2; half++) {
            int m = bm + wm + mt * 16 + gid + half * 8;
            if (m >= M) continue;
#pragma unroll
            for (int nt = 0; nt < 4; nt++) {
                int n = bn + wn + nt * 8 + 2 * tig;
                float v0 = acc[mt][nt][half * 2 + 0];
                float v1 = acc[mt][nt][half * 2 + 1];
                if (mode == 1) {
                    v0 += bias[n];
                    v1 += bias[n + 1];
                    v0 = v0 > 0.f ? v0 : expm1f(v0);
                    v1 = v1 > 0.f ? v1 : expm1f(v1);
                    *(float2*)&C[(size_t)m * N + n] = make_float2(v0, v1);
                } else {
                    *(__nv_bfloat162*)&Cb[(size_t)m * N + n] = __floats2bfloat162_rn(v0, v1);
                }
            }
        }
    }
}

// ---------------- attention logits: e_src / e_dst (bf16 features) ----------
__device__ __forceinline__ float2 b2f(uint32_t u) {
    __nv_bfloat162 h;
    *reinterpret_cast<uint32_t*>(&h) = u;
    return __bfloat1622float2(h);
}

template <int H, int D>
__global__ void compute_e_kernel(const __nv_bfloat16* __restrict__ xf,
                                 const float* __restrict__ a_s,
                                 const float* __restrict__ a_d) {
    constexpr int F = H * D;
    constexpr int FP = F / 32;
    int gw = (blockIdx.x * blockDim.x + threadIdx.x) >> 5;
    int lane = threadIdx.x & 31;
    if (gw >= N_NODES) return;
    const __nv_bfloat16* xr = xf + (size_t)gw * F;
    float ps = 0.f, pd = 0.f;
    if constexpr (FP == 8) {
        uint4 r = ((const uint4*)xr)[lane];
        float2 f0 = b2f(r.x), f1 = b2f(r.y), f2 = b2f(r.z), f3 = b2f(r.w);
        float vv[8] = {f0.x, f0.y, f1.x, f1.y, f2.x, f2.y, f3.x, f3.y};
#pragma unroll
        for (int q = 0; q < 8; q++) {
            int f = lane * 8 + q;
            ps += vv[q] * a_s[f];
            pd += vv[q] * a_d[f];
        }
    } else {
        uint32_t r = ((const uint32_t*)xr)[lane];
        float2 f = b2f(r);
        int f0 = lane * 2;
        ps += f.x * a_s[f0] + f.y * a_s[f0 + 1];
        pd += f.x * a_d[f0] + f.y * a_d[f0 + 1];
    }
    constexpr int G = 32 / H;
#pragma unroll
    for (int off = G >> 1; off; off >>= 1) {
        ps += __shfl_down_sync(0xffffffffu, ps, off);
        pd += __shfl_down_sync(0xffffffffu, pd, off);
    }
    if ((lane & (G - 1)) == 0) {
        int h = lane / G;
        g_esrc[gw * H + h] = ps;
        g_edst[gw * H + h] = pd;
    }
}

// ---------------- GAT aggregation (no max-shift, smem-staged, pipelined) ---
template <int H, int D>
__global__ __launch_bounds__(256) void gat_agg_kernel(
        const __nv_bfloat16* __restrict__ xf,
        const float* __restrict__ bias,
        float* __restrict__ out) {
    constexpr int F = H * D;
    constexpr int FP = F / 32;
    __shared__ float swv[8][32][H];
    __shared__ int   ssc[8][32];

    int wslot = threadIdx.x >> 5;
    int gw = (blockIdx.x * blockDim.x + threadIdx.x) >> 5;
    int lane = threadIdx.x & 31;
    if (gw >= N_NODES) return;
    const int i = gw;
    const int beg = g_offsets[i], end = g_offsets[i + 1];

    float edst_i[H], wself[H];
#pragma unroll
    for (int h = 0; h < H; h++) {
        edst_i[h] = g_edst[i * H + h];
        float v = g_esrc[i * H + h] + edst_i[h];
        v = v > 0.f ? v : 0.2f * v;
        wself[h] = __expf(v);
    }

    float acc[FP];
#pragma unroll
    for (int q = 0; q < FP; q++) acc[q] = 0.f;
    float ssum[H];
#pragma unroll
    for (int h = 0; h < H; h++) ssum[h] = 0.f;
    const int myh = (lane * FP) / D;

    for (int base = beg; base < end; base += 32) {
        int k = base + lane;
        int cnt = min(32, end - base);
        if (k < end) {
            int s = g_csr[k];
            ssc[wslot][lane] = s;
            float wv[H];
#pragma unroll
            for (int h = 0; h < H; h++) {
                float v = g_esrc[s * H + h] + edst_i[h];
                v = v > 0.f ? v : 0.2f * v;
                float ww = __expf(v);
                wv[h] = ww;
                ssum[h] += ww;
            }
            if constexpr (H == 4)
                *(float4*)&swv[wslot][lane][0] = make_float4(wv[0], wv[1], wv[2], wv[3]);
            else
                swv[wslot][lane][0] = wv[0];
        }
        __syncwarp();

        if constexpr (FP == 8) {
            uint4 cur;
            {
                int s0 = ssc[wslot][0];
                cur = ((const uint4*)(xf + (size_t)s0 * F))[lane];
            }
            for (int j = 0; j < cnt; j++) {
                float wh = swv[wslot][j][myh];
                uint4 nxt = cur;
                if (j + 1 < cnt) {
                    int sn = ssc[wslot][j + 1];
                    nxt = ((const uint4*)(xf + (size_t)sn * F))[lane];
                }
                float2 f0 = b2f(cur.x), f1 = b2f(cur.y), f2 = b2f(cur.z), f3 = b2f(cur.w);
                acc[0] += wh * f0.x; acc[1] += wh * f0.y;
                acc[2] += wh * f1.x; acc[3] += wh * f1.y;
                acc[4] += wh * f2.x; acc[5] += wh * f2.y;
                acc[6] += wh * f3.x; acc[7] += wh * f3.y;
                cur = nxt;
            }
        } else {
            uint32_t cur;
            {
                int s0 = ssc[wslot][0];
                cur = ((const uint32_t*)(xf + (size_t)s0 * F))[lane];
            }
            for (int j = 0; j < cnt; j++) {
                float wh = swv[wslot][j][0];
                uint32_t nxt = cur;
                if (j + 1 < cnt) {
                    int sn = ssc[wslot][j + 1];
                    nxt = ((const uint32_t*)(xf + (size_t)sn * F))[lane];
                }
                float2 f = b2f(cur);
                acc[0] += wh * f.x; acc[1] += wh * f.y;
                cur = nxt;
            }
        }
        __syncwarp();
    }

#pragma unroll
    for (int h = 0; h < H; h++)
#pragma unroll
        for (int off = 16; off; off >>= 1)
            ssum[h] += __shfl_xor_sync(0xffffffffu, ssum[h], off);
#pragma unroll
    for (int h = 0; h < H; h++) ssum[h] += wself[h];

    {
        float wh;
        if constexpr (H == 4)
            wh = (myh == 0) ? wself[0] : (myh == 1) ? wself[1] : (myh == 2) ? wself[2] : wself[3];
        else
            wh = wself[0];
        const __nv_bfloat16* xr = xf + (size_t)i * F;
        if constexpr (FP == 8) {
            uint4 r = ((const uint4*)xr)[lane];
            float2 f0 = b2f(r.x), f1 = b2f(r.y), f2 = b2f(r.z), f3 = b2f(r.w);
            acc[0] += wh * f0.x; acc[1] += wh * f0.y;
            acc[2] += wh * f1.x; acc[3] += wh * f1.y;
            acc[4] += wh * f2.x; acc[5] += wh * f2.y;
            acc[6] += wh * f3.x; acc[7] += wh * f3.y;
        } else {
            uint32_t r = ((const uint32_t*)xr)[lane];
            float2 f = b2f(r);
            acc[0] += wh * f.x; acc[1] += wh * f.y;
        }
    }

    float denom;
    if constexpr (H == 4)
        denom = (myh == 0) ? ssum[0] : (myh == 1) ? ssum[1] : (myh == 2) ? ssum[2] : ssum[3];
    else
        denom = ssum[0];
    float inv = 1.f / denom;
#pragma unroll
    for (int q = 0; q < FP; q++) {
        int f = lane * FP + q;
        float v = acc[q] * inv + bias[f];
        v = v > 0.f ? v : expm1f(v);
        out[(size_t)i * F + f] = v;
    }
}

// ---------------- global mean pool + output projection ---------------------
__global__ void pool_kernel(const float* __restrict__ h) {
    __shared__ float sacc[64];
    int t = threadIdx.x;
    if (t < 64) sacc[t] = 0.f;
    __syncthreads();
    int col = t & 63;
    int rpb = blockDim.x >> 6;
    float a = 0.f;
    for (int r = blockIdx.x * rpb + (t >> 6); r < N_NODES; r += gridDim.x * rpb)
        a += h[(size_t)r * 64 + col];
    atomicAdd(&sacc[col], a);
    __syncthreads();
    if (t < 64) atomicAdd(&g_pool[t], sacc[t]);
}

__global__ void final_kernel(const float* __restrict__ w_out,
                             const float* __restrict__ b_out,
                             float* __restrict__ out) {
    int j = threadIdx.x;
    float s = b_out[j];
    const float invn = 1.f / (float)N_NODES;
    for (int k = 0; k < 64; k++)
        s += g_pool[k] * invn * w_out[k * 128 + j];
    out[j] = s;
}

// ---------------- launcher -------------------------------------------------
extern "C" void kernel_launch(void* const* d_in, const int* in_sizes, int n_in,
                              void* d_out, int out_size) {
    const float* x     = (const float*)d_in[0];
    const int*   ei    = (const int*)d_in[1];
    const int*   src   = ei;
    const int*   dst   = ei + N_EDGES;
    const float* w_in  = (const float*)d_in[2];
    const float* b_in  = (const float*)d_in[3];
    const float* W0    = (const float*)d_in[4];
    const float* as0   = (const float*)d_in[5];
    const float* ad0   = (const float*)d_in[6];
    const float* bb0   = (const float*)d_in[7];
    const float* W1    = (const float*)d_in[8];
    const float* as1   = (const float*)d_in[9];
    const float* ad1   = (const float*)d_in[10];
    const float* bb1   = (const float*)d_in[11];
    const float* W2    = (const float*)d_in[12];
    const float* as2   = (const float*)d_in[13];
    const float* ad2   = (const float*)d_in[14];
    const float* bb2   = (const float*)d_in[15];
    const float* w_out = (const float*)d_in[16];
    const float* b_out = (const float*)d_in[17];
    float* out = (float*)d_out;

    void *p_h64, *p_xf, *p_hA, *p_hB;
    cudaGetSymbolAddress(&p_h64, g_h64);
    cudaGetSymbolAddress(&p_xf,  g_xf);
    cudaGetSymbolAddress(&p_hA,  g_hA);
    cudaGetSymbolAddress(&p_hB,  g_hB);
    float* h64 = (float*)p_h64;
    __nv_bfloat16* xf = (__nv_bfloat16*)p_xf;
    float* hA  = (float*)p_hA;
    float* hB  = (float*)p_hB;

    const int EB = (N_EDGES + 255) / 256;
    const int NB = (N_NODES + 255) / 256;
    const int MY = (N_NODES + 127) / 128;
    const int WARPB = N_NODES / 8;

    zero_kernel<<<NB, 256>>>();
    hist_kernel<<<EB, 256>>>(dst);
    scan_kernel<<<1, 1024>>>();
    scatter_kernel<<<EB, 256>>>(src, dst);

    tf32gemm_kernel<<<dim3(1, MY), 256>>>(x, w_in, b_in, h64, nullptr,
                                          N_NODES, 64, 256, 1);

    tf32gemm_kernel<<<dim3(4, MY), 256>>>(h64, W0, nullptr, nullptr, xf,
                                          N_NODES, 256, 64, 0);
    compute_e_kernel<4, 64><<<WARPB, 256>>>(xf, as0, ad0);
    gat_agg_kernel<4, 64><<<WARPB, 256>>>(xf, bb0, hA);

    tf32gemm_kernel<<<dim3(4, MY), 256>>>(hA, W1, nullptr, nullptr, xf,
                                          N_NODES, 256, 256, 0);
    compute_e_kernel<4, 64><<<WARPB, 256>>>(xf, as1, ad1);
    gat_agg_kernel<4, 64><<<WARPB, 256>>>(xf, bb1, hB);

    tf32gemm_kernel<<<dim3(1, MY), 256>>>(hB, W2, nullptr, nullptr, xf,
                                          N_NODES, 64, 256, 0);
    compute_e_kernel<1, 64><<<WARPB, 256>>>(xf, as2, ad2);
    gat_agg_kernel<1, 64><<<WARPB, 256>>>(xf, bb2, h64);

    pool_kernel<<<256, 256>>>(h64);
    final_kernel<<<1, 128>>>(w_out, b_out, out);
}